// round 14
// baseline (speedup 1.0000x reference)
#include <cuda_runtime.h>
#include <cuda_fp16.h>
#include <math.h>
#include <stdlib.h>
#include <stdint.h>

// Problem sizes (reference: N=100000, E=1200000)
#define NMAX 100000
#define EMAX 1200000
#define STATS_BLOCKS 256

namespace {
struct EagerLoad {
    EagerLoad() { setenv("CUDA_MODULE_LOADING", "EAGER", 1); }
};
static EagerLoad g_eager;
}  // namespace

// ---------------- device scratch (zero-initialized at module load; final_kernel
// re-zeroes g_degi/g_total each launch for the next graph replay) ----------------
__device__ int    g_total;
__device__ int    g_done;              // last-block-done counter (self-resetting)
__device__ int    g_degi[NMAX];
__device__ int    g_off[NMAX];
__device__ int    g_cur[NMAX];
__device__ int    g_srcs[EMAX];

__device__ float  g_mean[NMAX * 128];  // L1: mean1 (stride 64). L2: uv = [u|v] (stride 128)
__device__ float  g_h[NMAX * 128];     // layer1 pre-BN output

__device__ double g_ps[STATS_BLOCKS * 128];
__device__ double g_pq[STATS_BLOCKS * 128];
__device__ float  g_a1[128], g_bb1[128];
__device__ float  g_a2[64],  g_bb2[64];

// ---------------- CSR build (edges are int32: verified via fill DRAM traffic =
// 10.0MB = 2.4M x 4B, and harness dtype set {f32,i32,bf16}) ----------------
__global__ void __launch_bounds__(256, 1) hist_kernel(const int* __restrict__ dst_arr,
                                                      int E, int n) {
    int e = blockIdx.x * blockDim.x + threadIdx.x;
    if (e < E) {
        int d = dst_arr[e];
        d = min(max(d, 0), n - 1);
        atomicAdd(&g_degi[d], 1);
    }
}

// Bump-allocate contiguous segment per node (order irrelevant for gathering).
__global__ void __launch_bounds__(256, 1) alloc_kernel(int n) {
    int i = blockIdx.x * blockDim.x + threadIdx.x;
    if (i < n) {
        int off = atomicAdd(&g_total, g_degi[i]);
        g_off[i] = off;
        g_cur[i] = off;
    }
}

__global__ void __launch_bounds__(256, 1) fill_kernel(const int* __restrict__ src_arr,
                                                      const int* __restrict__ dst_arr,
                                                      int E, int n) {
    int e = blockIdx.x * blockDim.x + threadIdx.x;
    if (e < E) {
        int d = dst_arr[e];
        int s = src_arr[e];
        d = min(max(d, 0), n - 1);
        s = min(max(s, 0), n - 1);
        int p = atomicAdd(&g_cur[d], 1);
        g_srcs[p] = s;
    }
}

// ------- layer-1 mean aggregation: 16 lanes/node, float4 loads, predicated 4-wide -------
__global__ void __launch_bounds__(256, 1) agg64_kernel(const float* __restrict__ x, int n) {
    int t = blockIdx.x * blockDim.x + threadIdx.x;
    int w = t >> 4;
    int l = t & 15;
    if (w >= n) return;
    int s0 = g_off[w];
    int c = g_degi[w];
    const float4* x4 = (const float4*)x;  // row = 16 float4
    float ax = 0.f, ay = 0.f, az = 0.f, aw = 0.f;
    int last = s0 + c - 1;
    for (int j = 0; j < c; j += 4) {
        int ja = s0 + j;
        int sa = g_srcs[ja];
        int sb = g_srcs[min(ja + 1, last)];
        int sc = g_srcs[min(ja + 2, last)];
        int sd = g_srcs[min(ja + 3, last)];
        float mb = (j + 1 < c) ? 1.f : 0.f;
        float mc = (j + 2 < c) ? 1.f : 0.f;
        float md = (j + 3 < c) ? 1.f : 0.f;
        float4 va = x4[(size_t)sa * 16 + l];
        float4 vb = x4[(size_t)sb * 16 + l];
        float4 vc = x4[(size_t)sc * 16 + l];
        float4 vd = x4[(size_t)sd * 16 + l];
        ax += va.x + mb * vb.x + mc * vc.x + md * vd.x;
        ay += va.y + mb * vb.y + mc * vc.y + md * vd.y;
        az += va.z + mb * vb.z + mc * vc.z + md * vd.z;
        aw += va.w + mb * vb.w + mc * vc.w + md * vd.w;
    }
    float inv = 1.0f / (float)max(c, 1);
    ((float4*)g_mean)[(size_t)w * 16 + l] =
        make_float4(ax * inv, ay * inv, az * inv, aw * inv);
}

// -- layer-2: out0 = mean_agg(u) + bl2 + v; uv=[u|v] in g_mean (stride 128) --
__global__ void __launch_bounds__(256, 1) agg2_kernel(const float* __restrict__ bl2,
                                                      float* __restrict__ out0, int n) {
    int t = blockIdx.x * blockDim.x + threadIdx.x;
    int w = t >> 4;
    int l = t & 15;
    if (w >= n) return;
    int s0 = g_off[w];
    int c = g_degi[w];
    const float4* uv4 = (const float4*)g_mean;  // row = 32 float4; u at 0..15, v at 16..31
    float ax = 0.f, ay = 0.f, az = 0.f, aw = 0.f;
    int last = s0 + c - 1;
    for (int j = 0; j < c; j += 4) {
        int ja = s0 + j;
        int sa = g_srcs[ja];
        int sb = g_srcs[min(ja + 1, last)];
        int sc = g_srcs[min(ja + 2, last)];
        int sd = g_srcs[min(ja + 3, last)];
        float mb = (j + 1 < c) ? 1.f : 0.f;
        float mc = (j + 2 < c) ? 1.f : 0.f;
        float md = (j + 3 < c) ? 1.f : 0.f;
        float4 va = uv4[(size_t)sa * 32 + l];
        float4 vb = uv4[(size_t)sb * 32 + l];
        float4 vc = uv4[(size_t)sc * 32 + l];
        float4 vd = uv4[(size_t)sd * 32 + l];
        ax += va.x + mb * vb.x + mc * vc.x + md * vd.x;
        ay += va.y + mb * vb.y + mc * vc.y + md * vd.y;
        az += va.z + mb * vb.z + mc * vc.z + md * vd.z;
        aw += va.w + mb * vb.w + mc * vc.w + md * vd.w;
    }
    float inv = 1.0f / (float)max(c, 1);
    float4 v  = uv4[(size_t)w * 32 + 16 + l];
    float4 bl = ((const float4*)bl2)[l];
    ((float4*)out0)[(size_t)w * 16 + l] =
        make_float4(fmaf(ax, inv, bl.x) + v.x, fmaf(ay, inv, bl.y) + v.y,
                    fmaf(az, inv, bl.z) + v.z, fmaf(aw, inv, bl.w) + v.w);
}

// ---------------- f16 packing ----------------
__device__ __forceinline__ uint32_t pack_h2(float a, float b) {
    __half2 h = __floats2half2_rn(a, b);
    return *(uint32_t*)&h;
}

// ---------------- GEMM via f16 mma.sync m16n8k16: 128x128 tile, K=128 ----------------
// MODE 1: g_h[N,128]   = [g_mean|x] @ [Wl1|Wr1]^T + bl1   (A strides 64; W [128,64])
// MODE 2: g_mean[N,128]= bnrelu(g_h) @ [Wl2|Wr2]^T        (A stride 128; W [64,128])
#define APITCH 68
template <int MODE>
__global__ void __launch_bounds__(256, 1)
gemm_kernel(const float* __restrict__ xarg,
            const float* __restrict__ W0, const float* __restrict__ W1,
            const float* __restrict__ bias, int n) {
    extern __shared__ uint32_t smem_u[];
    uint32_t* a_s = smem_u;
    uint32_t* b_s = smem_u + 128 * APITCH;

    int tid  = threadIdx.x;
    int lane = tid & 31;
    int wid  = tid >> 5;
    int g    = lane >> 2;
    int t    = lane & 3;
    int blockRow = blockIdx.x * 128;

    for (int f = tid; f < 4096; f += 256) {
        int r  = f >> 5;
        int k0 = (f & 31) * 4;
        int row = blockRow + r;
        float4 v = make_float4(0.f, 0.f, 0.f, 0.f);
        if (row < n) {
            if (MODE == 1) {
                const float* Ab = (k0 < 64) ? g_mean : xarg;
                v = *(const float4*)(Ab + (size_t)row * 64 + (k0 & 63));
            } else {
                v = *(const float4*)(g_h + (size_t)row * 128 + k0);
                float4 ca = *(const float4*)&g_a1[k0];
                float4 cb = *(const float4*)&g_bb1[k0];
                v.x = fmaxf(fmaf(ca.x, v.x, cb.x), 0.f);
                v.y = fmaxf(fmaf(ca.y, v.y, cb.y), 0.f);
                v.z = fmaxf(fmaf(ca.z, v.z, cb.z), 0.f);
                v.w = fmaxf(fmaf(ca.w, v.w, cb.w), 0.f);
            }
        }
        uint2 pk = make_uint2(pack_h2(v.x, v.y), pack_h2(v.z, v.w));
        *(uint2*)&a_s[r * APITCH + (k0 >> 1)] = pk;
    }
    for (int f = tid; f < 4096; f += 256) {
        int c  = f >> 5;
        int k0 = (f & 31) * 4;
        float4 v;
        if (MODE == 1) {
            const float* Wb = (k0 < 64) ? W0 : W1;   // [128,64]
            v = *(const float4*)(Wb + (size_t)c * 64 + (k0 & 63));
        } else {
            const float* wr = (c < 64) ? (W0 + (size_t)c * 128)
                                       : (W1 + (size_t)(c - 64) * 128);  // [64,128]
            v = *(const float4*)(wr + k0);
        }
        uint2 pk = make_uint2(pack_h2(v.x, v.y), pack_h2(v.z, v.w));
        *(uint2*)&b_s[c * APITCH + (k0 >> 1)] = pk;
    }
    __syncthreads();

    float acc[16][4];
#pragma unroll
    for (int j = 0; j < 16; j++)
#pragma unroll
        for (int p = 0; p < 4; p++) acc[j][p] = 0.f;

    int base_a0 = (wid * 16 + g) * APITCH + t;
    int base_a1 = base_a0 + 8 * APITCH;
#pragma unroll
    for (int kk = 0; kk < 8; kk++) {
        int o = kk * 8;
        uint32_t A0 = a_s[base_a0 + o];
        uint32_t A1 = a_s[base_a1 + o];
        uint32_t A2 = a_s[base_a0 + o + 4];
        uint32_t A3 = a_s[base_a1 + o + 4];
#pragma unroll
        for (int j = 0; j < 16; j++) {
            int bidx = (j * 8 + g) * APITCH + o;
            uint32_t B0 = b_s[bidx + t];
            uint32_t B1 = b_s[bidx + t + 4];
            asm volatile(
                "mma.sync.aligned.m16n8k16.row.col.f32.f16.f16.f32 "
                "{%0,%1,%2,%3},{%4,%5,%6,%7},{%8,%9},{%0,%1,%2,%3};"
                : "+f"(acc[j][0]), "+f"(acc[j][1]), "+f"(acc[j][2]), "+f"(acc[j][3])
                : "r"(A0), "r"(A1), "r"(A2), "r"(A3), "r"(B0), "r"(B1));
        }
    }

    float* out = (MODE == 1) ? g_h : g_mean;
    int r0 = blockRow + wid * 16 + g;
#pragma unroll
    for (int j = 0; j < 16; j++) {
        int col = j * 8 + t * 2;
        float bx = 0.f, by = 0.f;
        if (MODE == 1) {
            float2 bb = *(const float2*)(bias + col);
            bx = bb.x; by = bb.y;
        }
        if (r0 < n)
            *(float2*)(out + (size_t)r0 * 128 + col) =
                make_float2(acc[j][0] + bx, acc[j][1] + by);
        if (r0 + 8 < n)
            *(float2*)(out + (size_t)(r0 + 8) * 128 + col) =
                make_float2(acc[j][2] + bx, acc[j][3] + by);
    }
}

// ---------------- fused BN stats + finalize (last-block-done) ----------------
template <int C>
__device__ __forceinline__ void statsfin_body(const float* __restrict__ src, int n,
                                              const float* __restrict__ gamma,
                                              const float* __restrict__ beta,
                                              float* a_out, float* b_out) {
    constexpr int SUB = 256 / C;
    int tid = threadIdx.x;
    int c = tid % C;
    int sub = tid / C;
    double s = 0.0, q = 0.0;
    for (int r = blockIdx.x * SUB + sub; r < n; r += gridDim.x * SUB) {
        float v = src[(size_t)r * C + c];
        s += (double)v;
        q += (double)v * (double)v;
    }
    __shared__ double sh[256];
    sh[tid] = s;
    __syncthreads();
    if (sub == 0) {
        double ss = s;
        for (int k = 1; k < SUB; k++) ss += sh[tid + k * C];
        g_ps[blockIdx.x * C + c] = ss;
    }
    __syncthreads();
    sh[tid] = q;
    __syncthreads();
    if (sub == 0) {
        double qq = q;
        for (int k = 1; k < SUB; k++) qq += sh[tid + k * C];
        g_pq[blockIdx.x * C + c] = qq;
        __threadfence();
    }
    __shared__ int lastFlag;
    __syncthreads();
    if (tid == 0) {
        int v = atomicAdd(&g_done, 1);
        lastFlag = (v == (int)gridDim.x - 1);
    }
    __syncthreads();
    if (!lastFlag) return;

    if (tid == 0) g_done = 0;
    __threadfence();
    int col = tid % C;
    int part = tid / C;
    const int PARTS = 256 / C;
    double ss = 0.0, qq = 0.0;
    for (int b = part; b < (int)gridDim.x; b += PARTS) {
        ss += g_ps[b * C + col];
        qq += g_pq[b * C + col];
    }
    sh[tid] = ss;
    __syncthreads();
    if (part == 0)
        for (int k = 1; k < PARTS; k++) ss += sh[col + k * C];
    __syncthreads();
    sh[tid] = qq;
    __syncthreads();
    if (part == 0) {
        for (int k = 1; k < PARTS; k++) qq += sh[col + k * C];
        double mu = ss / (double)n;
        double var = qq / (double)n - mu * mu;
        if (var < 0.0) var = 0.0;
        float ai = gamma[col] * rsqrtf((float)var + 1e-5f);
        a_out[col] = ai;
        b_out[col] = beta[col] - (float)mu * ai;
    }
}

__global__ void __launch_bounds__(256, 1) statsfin128_kernel(const float* __restrict__ gamma,
                                                             const float* __restrict__ beta,
                                                             int n) {
    statsfin_body<128>(g_h, n, gamma, beta, g_a1, g_bb1);
}
__global__ void __launch_bounds__(256, 1) statsfin64_kernel(const float* __restrict__ src,
                                                            const float* __restrict__ gamma,
                                                            const float* __restrict__ beta,
                                                            int n) {
    statsfin_body<64>(src, n, gamma, beta, g_a2, g_bb2);
}

// ---- final: BN2+ReLU on out0, FC+softmax -> out1; also resets CSR state for next replay ----
__global__ void __launch_bounds__(256, 1) final_kernel(const float* __restrict__ Wfc,
                                                       const float* __restrict__ bfc,
                                                       float* __restrict__ out0,
                                                       float* __restrict__ out1, int n) {
    int gi = blockIdx.x * blockDim.x + threadIdx.x;
    if (gi < n) g_degi[gi] = 0;      // pre-zero for next replay's hist
    if (gi == 0) g_total = 0;

    int w = gi >> 5;
    int lane = gi & 31;
    if (w >= n) return;
    float2 v = ((const float2*)out0)[(size_t)w * 32 + lane];
    float2 a = ((const float2*)g_a2)[lane];
    float2 b = ((const float2*)g_bb2)[lane];
    v.x = fmaxf(fmaf(a.x, v.x, b.x), 0.f);
    v.y = fmaxf(fmaf(a.y, v.y, b.y), 0.f);
    ((float2*)out0)[(size_t)w * 32 + lane] = v;

    float2 w0 = ((const float2*)Wfc)[lane];
    float2 w1 = ((const float2*)Wfc)[32 + lane];
    float d0 = v.x * w0.x + v.y * w0.y;
    float d1 = v.x * w1.x + v.y * w1.y;
#pragma unroll
    for (int off = 16; off > 0; off >>= 1) {
        d0 += __shfl_down_sync(0xFFFFFFFFu, d0, off);
        d1 += __shfl_down_sync(0xFFFFFFFFu, d1, off);
    }
    if (lane == 0) {
        float l0 = d0 + bfc[0];
        float l1 = d1 + bfc[1];
        float m = fmaxf(l0, l1);
        float e0 = __expf(l0 - m);
        float e1 = __expf(l1 - m);
        float inv = 1.0f / (e0 + e1);
        out1[(size_t)w * 2 + 0] = e0 * inv;
        out1[(size_t)w * 2 + 1] = e1 * inv;
    }
}

// ---------------- launch ----------------
// NOTE: no device symbol (g_*) may ever appear as a kernel ARGUMENT here.
extern "C" void kernel_launch(void* const* d_in, const int* in_sizes, int n_in,
                              void* d_out, int out_size) {
    const float* x = (const float*)d_in[0];
    int n = in_sizes[0] / 64;
    if (n > NMAX) n = NMAX;

    const int* src_arr;
    const int* dst_arr;
    int E, wbase;
    if (n_in >= 15) {
        src_arr = (const int*)d_in[1];
        dst_arr = (const int*)d_in[2];
        E = in_sizes[1];
        wbase = 3;
    } else {
        E = in_sizes[1] / 2;
        src_arr = (const int*)d_in[1];
        dst_arr = src_arr + E;
        wbase = 2;
    }
    if (E > EMAX) E = EMAX;

    const float* Wl1 = (const float*)d_in[wbase + 0];
    const float* bl1 = (const float*)d_in[wbase + 1];
    const float* Wr1 = (const float*)d_in[wbase + 2];
    const float* g1  = (const float*)d_in[wbase + 3];
    const float* b1  = (const float*)d_in[wbase + 4];
    const float* Wl2 = (const float*)d_in[wbase + 5];
    const float* bl2 = (const float*)d_in[wbase + 6];
    const float* Wr2 = (const float*)d_in[wbase + 7];
    const float* g2  = (const float*)d_in[wbase + 8];
    const float* b2  = (const float*)d_in[wbase + 9];
    const float* Wfc = (const float*)d_in[wbase + 10];
    const float* bfc = (const float*)d_in[wbase + 11];

    float* out0 = (float*)d_out;
    float* out1 = out0 + (size_t)n * 64;

    int agg16Grid = (int)(((size_t)n * 16 + 255) / 256);
    int warpGrid  = (int)(((size_t)n * 32 + 255) / 256);
    int gemmGrid = (n + 127) / 128;
    const int GEMM_SMEM = 2 * 128 * APITCH * 4;  // 69632 B

    cudaFuncSetAttribute(gemm_kernel<1>, cudaFuncAttributeMaxDynamicSharedMemorySize, GEMM_SMEM);
    cudaFuncSetAttribute(gemm_kernel<2>, cudaFuncAttributeMaxDynamicSharedMemorySize, GEMM_SMEM);

    hist_kernel<<<(E + 255) / 256, 256>>>(dst_arr, E, n);
    alloc_kernel<<<(n + 255) / 256, 256>>>(n);
    fill_kernel<<<(E + 255) / 256, 256>>>(src_arr, dst_arr, E, n);

    // layer 1 (agg64 is the 4th launch -> profiled by ncu)
    agg64_kernel<<<agg16Grid, 256>>>(x, n);
    gemm_kernel<1><<<gemmGrid, 256, GEMM_SMEM>>>(x, Wl1, Wr1, bl1, n);
    statsfin128_kernel<<<STATS_BLOCKS, 256>>>(g1, b1, n);

    // layer 2
    gemm_kernel<2><<<gemmGrid, 256, GEMM_SMEM>>>(nullptr, Wl2, Wr2, nullptr, n);
    agg2_kernel<<<agg16Grid, 256>>>(bl2, out0, n);
    statsfin64_kernel<<<STATS_BLOCKS, 256>>>(out0, g2, b2, n);

    final_kernel<<<warpGrid, 256>>>(Wfc, bfc, out0, out1, n);
}

// round 16
// speedup vs baseline: 1.0903x; 1.0903x over previous
#include <cuda_runtime.h>
#include <cuda_fp16.h>
#include <math.h>
#include <stdlib.h>
#include <stdint.h>

// Problem sizes (reference: N=100000, E=1200000)
#define NMAX 100000
#define EMAX 1200000
#define STATS_BLOCKS 256

namespace {
struct EagerLoad {
    EagerLoad() { setenv("CUDA_MODULE_LOADING", "EAGER", 1); }
};
static EagerLoad g_eager;
}  // namespace

// ---------------- device scratch (zero-initialized at load; final_kernel re-zeroes
// g_degi/g_total each launch for the next graph replay) ----------------
__device__ int    g_total;
__device__ int    g_done;
__device__ int    g_degi[NMAX];
__device__ int    g_off[NMAX];
__device__ int    g_cur[NMAX];
__device__ int    g_srcs[EMAX];

__device__ __half g_xh[NMAX * 64];     // half(x)
__device__ __half g_meanh[NMAX * 64];  // half(mean1)
__device__ __half g_uh[NMAX * 64];     // half(u) from gemm2
__device__ float  g_v[NMAX * 64];      // v (fp32) from gemm2
__device__ float  g_h[NMAX * 128];     // layer1 pre-BN output (fp32)

__device__ double g_ps[STATS_BLOCKS * 128];
__device__ double g_pq[STATS_BLOCKS * 128];
__device__ float  g_a1[128], g_bb1[128];
__device__ float  g_a2[64],  g_bb2[64];

// ---------------- CSR build (edges are int32: fill DRAM traffic 10.0MB = 2.4M x 4B) ------
__global__ void __launch_bounds__(256, 1) hist_kernel(const int* __restrict__ dst_arr,
                                                      int E, int n) {
    int e = blockIdx.x * blockDim.x + threadIdx.x;
    if (e < E) {
        int d = dst_arr[e];
        d = min(max(d, 0), n - 1);
        atomicAdd(&g_degi[d], 1);
    }
}

// Bump-allocate per-node segments + convert x to half (fused; grid covers n*32).
__global__ void __launch_bounds__(256, 1) alloc_cvt_kernel(const float* __restrict__ x, int n) {
    int i = blockIdx.x * blockDim.x + threadIdx.x;
    if (i < n * 32) {   // n*64 halves = n*32 half2
        float2 v = ((const float2*)x)[i];
        ((__half2*)g_xh)[i] = __floats2half2_rn(v.x, v.y);
    }
    if (i < n) {
        int off = atomicAdd(&g_total, g_degi[i]);
        g_off[i] = off;
        g_cur[i] = off;
    }
}

__global__ void __launch_bounds__(256, 1) fill_kernel(const int* __restrict__ src_arr,
                                                      const int* __restrict__ dst_arr,
                                                      int E, int n) {
    int e = blockIdx.x * blockDim.x + threadIdx.x;
    if (e < E) {
        int d = dst_arr[e];
        int s = src_arr[e];
        d = min(max(d, 0), n - 1);
        s = min(max(s, 0), n - 1);
        int p = atomicAdd(&g_cur[d], 1);
        g_srcs[p] = s;
    }
}

// ---- layer-1 mean aggregation over half rows: 16 lanes/node, uint2 (4 halves)/lane ----
__global__ void __launch_bounds__(256, 1) agg64_kernel(int n) {
    int t = blockIdx.x * blockDim.x + threadIdx.x;
    int w = t >> 4;
    int l = t & 15;
    if (w >= n) return;
    int s0 = g_off[w];
    int c = g_degi[w];
    const uint2* xh2 = (const uint2*)g_xh;  // row = 16 uint2 (64 halves)
    float ax = 0.f, ay = 0.f, az = 0.f, aw = 0.f;
    int last = s0 + c - 1;
    for (int j = 0; j < c; j += 4) {
        int ja = s0 + j;
        int ia = g_srcs[ja] * 16 + l;
        int ib = g_srcs[min(ja + 1, last)] * 16 + l;
        int ic = g_srcs[min(ja + 2, last)] * 16 + l;
        int id = g_srcs[min(ja + 3, last)] * 16 + l;
        float mb = (j + 1 < c) ? 1.f : 0.f;
        float mc = (j + 2 < c) ? 1.f : 0.f;
        float md = (j + 3 < c) ? 1.f : 0.f;
        uint2 pa = xh2[ia];
        uint2 pb = xh2[ib];
        uint2 pc = xh2[ic];
        uint2 pd = xh2[id];
        float2 a0 = __half22float2(*(__half2*)&pa.x), a1 = __half22float2(*(__half2*)&pa.y);
        float2 b0 = __half22float2(*(__half2*)&pb.x), b1 = __half22float2(*(__half2*)&pb.y);
        float2 c0 = __half22float2(*(__half2*)&pc.x), c1 = __half22float2(*(__half2*)&pc.y);
        float2 d0 = __half22float2(*(__half2*)&pd.x), d1 = __half22float2(*(__half2*)&pd.y);
        ax += a0.x + mb * b0.x + mc * c0.x + md * d0.x;
        ay += a0.y + mb * b0.y + mc * c0.y + md * d0.y;
        az += a1.x + mb * b1.x + mc * c1.x + md * d1.x;
        aw += a1.y + mb * b1.y + mc * c1.y + md * d1.y;
    }
    float inv = 1.0f / (float)max(c, 1);
    uint2 o;
    __half2 h0 = __floats2half2_rn(ax * inv, ay * inv);
    __half2 h1 = __floats2half2_rn(az * inv, aw * inv);
    o.x = *(uint32_t*)&h0;
    o.y = *(uint32_t*)&h1;
    ((uint2*)g_meanh)[w * 16 + l] = o;
}

// -- layer-2: out0 = mean_agg(u_half) + bl2 + v_fp32 --
__global__ void __launch_bounds__(256, 1) agg2_kernel(const float* __restrict__ bl2,
                                                      float* __restrict__ out0, int n) {
    int t = blockIdx.x * blockDim.x + threadIdx.x;
    int w = t >> 4;
    int l = t & 15;
    if (w >= n) return;
    int s0 = g_off[w];
    int c = g_degi[w];
    const uint2* uh2 = (const uint2*)g_uh;  // row = 16 uint2
    float ax = 0.f, ay = 0.f, az = 0.f, aw = 0.f;
    int last = s0 + c - 1;
    for (int j = 0; j < c; j += 4) {
        int ja = s0 + j;
        int ia = g_srcs[ja] * 16 + l;
        int ib = g_srcs[min(ja + 1, last)] * 16 + l;
        int ic = g_srcs[min(ja + 2, last)] * 16 + l;
        int id = g_srcs[min(ja + 3, last)] * 16 + l;
        float mb = (j + 1 < c) ? 1.f : 0.f;
        float mc = (j + 2 < c) ? 1.f : 0.f;
        float md = (j + 3 < c) ? 1.f : 0.f;
        uint2 pa = uh2[ia];
        uint2 pb = uh2[ib];
        uint2 pc = uh2[ic];
        uint2 pd = uh2[id];
        float2 a0 = __half22float2(*(__half2*)&pa.x), a1 = __half22float2(*(__half2*)&pa.y);
        float2 b0 = __half22float2(*(__half2*)&pb.x), b1 = __half22float2(*(__half2*)&pb.y);
        float2 c0 = __half22float2(*(__half2*)&pc.x), c1 = __half22float2(*(__half2*)&pc.y);
        float2 d0 = __half22float2(*(__half2*)&pd.x), d1 = __half22float2(*(__half2*)&pd.y);
        ax += a0.x + mb * b0.x + mc * c0.x + md * d0.x;
        ay += a0.y + mb * b0.y + mc * c0.y + md * d0.y;
        az += a1.x + mb * b1.x + mc * c1.x + md * d1.x;
        aw += a1.y + mb * b1.y + mc * c1.y + md * d1.y;
    }
    float inv = 1.0f / (float)max(c, 1);
    float4 v  = ((const float4*)g_v)[w * 16 + l];
    float4 bl = ((const float4*)bl2)[l];
    ((float4*)out0)[w * 16 + l] =
        make_float4(fmaf(ax, inv, bl.x) + v.x, fmaf(ay, inv, bl.y) + v.y,
                    fmaf(az, inv, bl.z) + v.z, fmaf(aw, inv, bl.w) + v.w);
}

// ---------------- f16 packing ----------------
__device__ __forceinline__ uint32_t pack_h2(float a, float b) {
    __half2 h = __floats2half2_rn(a, b);
    return *(uint32_t*)&h;
}

// ---------------- GEMM via f16 mma.sync m16n8k16: 128x128 tile, K=128 ----------------
// MODE 1: g_h[N,128] = [meanh|xh] @ [Wl1|Wr1]^T + bl1  (A already half; W [128,64])
// MODE 2: u,v        = bnrelu(g_h) @ [Wl2|Wr2]^T       (A fp32+BN; W [64,128];
//                      cols 0..63 -> g_uh (half), cols 64..127 -> g_v (fp32))
#define APITCH 68
template <int MODE>
__global__ void __launch_bounds__(256, 1)
gemm_kernel(const float* __restrict__ W0, const float* __restrict__ W1,
            const float* __restrict__ bias, int n) {
    extern __shared__ uint32_t smem_u[];
    uint32_t* a_s = smem_u;
    uint32_t* b_s = smem_u + 128 * APITCH;

    int tid  = threadIdx.x;
    int lane = tid & 31;
    int wid  = tid >> 5;
    int g    = lane >> 2;
    int t    = lane & 3;
    int blockRow = blockIdx.x * 128;

    // ---- A tile fill ----
    for (int f = tid; f < 4096; f += 256) {
        int r  = f >> 5;
        int k0 = (f & 31) * 4;
        int row = blockRow + r;
        uint2 pk = make_uint2(0u, 0u);
        if (row < n) {
            if (MODE == 1) {
                const __half* Ab = (k0 < 64) ? g_meanh : g_xh;
                pk = *(const uint2*)(Ab + row * 64 + (k0 & 63));
            } else {
                float4 v = *(const float4*)(g_h + (size_t)row * 128 + k0);
                float4 ca = *(const float4*)&g_a1[k0];
                float4 cb = *(const float4*)&g_bb1[k0];
                v.x = fmaxf(fmaf(ca.x, v.x, cb.x), 0.f);
                v.y = fmaxf(fmaf(ca.y, v.y, cb.y), 0.f);
                v.z = fmaxf(fmaf(ca.z, v.z, cb.z), 0.f);
                v.w = fmaxf(fmaf(ca.w, v.w, cb.w), 0.f);
                pk = make_uint2(pack_h2(v.x, v.y), pack_h2(v.z, v.w));
            }
        }
        *(uint2*)&a_s[r * APITCH + (k0 >> 1)] = pk;
    }
    // ---- B tile fill ----
    for (int f = tid; f < 4096; f += 256) {
        int c  = f >> 5;
        int k0 = (f & 31) * 4;
        float4 v;
        if (MODE == 1) {
            const float* Wb = (k0 < 64) ? W0 : W1;   // [128,64]
            v = *(const float4*)(Wb + c * 64 + (k0 & 63));
        } else {
            const float* wr = (c < 64) ? (W0 + c * 128)
                                       : (W1 + (c - 64) * 128);  // [64,128]
            v = *(const float4*)(wr + k0);
        }
        uint2 pk = make_uint2(pack_h2(v.x, v.y), pack_h2(v.z, v.w));
        *(uint2*)&b_s[c * APITCH + (k0 >> 1)] = pk;
    }
    __syncthreads();

    float acc[16][4];
#pragma unroll
    for (int j = 0; j < 16; j++)
#pragma unroll
        for (int p = 0; p < 4; p++) acc[j][p] = 0.f;

    int base_a0 = (wid * 16 + g) * APITCH + t;
    int base_a1 = base_a0 + 8 * APITCH;
#pragma unroll
    for (int kk = 0; kk < 8; kk++) {
        int o = kk * 8;
        uint32_t A0 = a_s[base_a0 + o];
        uint32_t A1 = a_s[base_a1 + o];
        uint32_t A2 = a_s[base_a0 + o + 4];
        uint32_t A3 = a_s[base_a1 + o + 4];
#pragma unroll
        for (int j = 0; j < 16; j++) {
            int bidx = (j * 8 + g) * APITCH + o;
            uint32_t B0 = b_s[bidx + t];
            uint32_t B1 = b_s[bidx + t + 4];
            asm volatile(
                "mma.sync.aligned.m16n8k16.row.col.f32.f16.f16.f32 "
                "{%0,%1,%2,%3},{%4,%5,%6,%7},{%8,%9},{%0,%1,%2,%3};"
                : "+f"(acc[j][0]), "+f"(acc[j][1]), "+f"(acc[j][2]), "+f"(acc[j][3])
                : "r"(A0), "r"(A1), "r"(A2), "r"(A3), "r"(B0), "r"(B1));
        }
    }

    int r0 = blockRow + wid * 16 + g;
#pragma unroll
    for (int j = 0; j < 16; j++) {
        int col = j * 8 + t * 2;
        if (MODE == 1) {
            float2 bb = *(const float2*)(bias + col);
            if (r0 < n)
                *(float2*)(g_h + (size_t)r0 * 128 + col) =
                    make_float2(acc[j][0] + bb.x, acc[j][1] + bb.y);
            if (r0 + 8 < n)
                *(float2*)(g_h + (size_t)(r0 + 8) * 128 + col) =
                    make_float2(acc[j][2] + bb.x, acc[j][3] + bb.y);
        } else {
            if (col < 64) {   // u -> half
                if (r0 < n)
                    ((uint32_t*)g_uh)[r0 * 32 + (col >> 1)] = pack_h2(acc[j][0], acc[j][1]);
                if (r0 + 8 < n)
                    ((uint32_t*)g_uh)[(r0 + 8) * 32 + (col >> 1)] = pack_h2(acc[j][2], acc[j][3]);
            } else {          // v -> fp32
                int vc = col - 64;
                if (r0 < n)
                    *(float2*)(g_v + r0 * 64 + vc) = make_float2(acc[j][0], acc[j][1]);
                if (r0 + 8 < n)
                    *(float2*)(g_v + (r0 + 8) * 64 + vc) = make_float2(acc[j][2], acc[j][3]);
            }
        }
    }
}

// ---------------- fused BN stats + finalize (last-block-done) ----------------
template <int C>
__device__ __forceinline__ void statsfin_body(const float* __restrict__ src, int n,
                                              const float* __restrict__ gamma,
                                              const float* __restrict__ beta,
                                              float* a_out, float* b_out) {
    constexpr int SUB = 256 / C;
    int tid = threadIdx.x;
    int c = tid % C;
    int sub = tid / C;
    double s = 0.0, q = 0.0;
    for (int r = blockIdx.x * SUB + sub; r < n; r += gridDim.x * SUB) {
        float v = src[(size_t)r * C + c];
        s += (double)v;
        q += (double)v * (double)v;
    }
    __shared__ double sh[256];
    sh[tid] = s;
    __syncthreads();
    if (sub == 0) {
        double ss = s;
        for (int k = 1; k < SUB; k++) ss += sh[tid + k * C];
        g_ps[blockIdx.x * C + c] = ss;
    }
    __syncthreads();
    sh[tid] = q;
    __syncthreads();
    if (sub == 0) {
        double qq = q;
        for (int k = 1; k < SUB; k++) qq += sh[tid + k * C];
        g_pq[blockIdx.x * C + c] = qq;
        __threadfence();
    }
    __shared__ int lastFlag;
    __syncthreads();
    if (tid == 0) {
        int v = atomicAdd(&g_done, 1);
        lastFlag = (v == (int)gridDim.x - 1);
    }
    __syncthreads();
    if (!lastFlag) return;

    if (tid == 0) g_done = 0;
    __threadfence();
    int col = tid % C;
    int part = tid / C;
    const int PARTS = 256 / C;
    double ss = 0.0, qq = 0.0;
    for (int b = part; b < (int)gridDim.x; b += PARTS) {
        ss += g_ps[b * C + col];
        qq += g_pq[b * C + col];
    }
    sh[tid] = ss;
    __syncthreads();
    if (part == 0)
        for (int k = 1; k < PARTS; k++) ss += sh[col + k * C];
    __syncthreads();
    sh[tid] = qq;
    __syncthreads();
    if (part == 0) {
        for (int k = 1; k < PARTS; k++) qq += sh[col + k * C];
        double mu = ss / (double)n;
        double var = qq / (double)n - mu * mu;
        if (var < 0.0) var = 0.0;
        float ai = gamma[col] * rsqrtf((float)var + 1e-5f);
        a_out[col] = ai;
        b_out[col] = beta[col] - (float)mu * ai;
    }
}

__global__ void __launch_bounds__(256, 1) statsfin128_kernel(const float* __restrict__ gamma,
                                                             const float* __restrict__ beta,
                                                             int n) {
    statsfin_body<128>(g_h, n, gamma, beta, g_a1, g_bb1);
}
__global__ void __launch_bounds__(256, 1) statsfin64_kernel(const float* __restrict__ src,
                                                            const float* __restrict__ gamma,
                                                            const float* __restrict__ beta,
                                                            int n) {
    statsfin_body<64>(src, n, gamma, beta, g_a2, g_bb2);
}

// ---- final: BN2+ReLU on out0, FC+softmax -> out1; resets CSR state for next replay ----
__global__ void __launch_bounds__(256, 1) final_kernel(const float* __restrict__ Wfc,
                                                       const float* __restrict__ bfc,
                                                       float* __restrict__ out0,
                                                       float* __restrict__ out1, int n) {
    int gi = blockIdx.x * blockDim.x + threadIdx.x;
    if (gi < n) g_degi[gi] = 0;
    if (gi == 0) g_total = 0;

    int w = gi >> 5;
    int lane = gi & 31;
    if (w >= n) return;
    float2 v = ((const float2*)out0)[(size_t)w * 32 + lane];
    float2 a = ((const float2*)g_a2)[lane];
    float2 b = ((const float2*)g_bb2)[lane];
    v.x = fmaxf(fmaf(a.x, v.x, b.x), 0.f);
    v.y = fmaxf(fmaf(a.y, v.y, b.y), 0.f);
    ((float2*)out0)[(size_t)w * 32 + lane] = v;

    float2 w0 = ((const float2*)Wfc)[lane];
    float2 w1 = ((const float2*)Wfc)[32 + lane];
    float d0 = v.x * w0.x + v.y * w0.y;
    float d1 = v.x * w1.x + v.y * w1.y;
#pragma unroll
    for (int off = 16; off > 0; off >>= 1) {
        d0 += __shfl_down_sync(0xFFFFFFFFu, d0, off);
        d1 += __shfl_down_sync(0xFFFFFFFFu, d1, off);
    }
    if (lane == 0) {
        float l0 = d0 + bfc[0];
        float l1 = d1 + bfc[1];
        float m = fmaxf(l0, l1);
        float e0 = __expf(l0 - m);
        float e1 = __expf(l1 - m);
        float inv = 1.0f / (e0 + e1);
        out1[(size_t)w * 2 + 0] = e0 * inv;
        out1[(size_t)w * 2 + 1] = e1 * inv;
    }
}

// ---------------- launch ----------------
// NOTE: no device symbol (g_*) may ever appear as a kernel ARGUMENT here.
extern "C" void kernel_launch(void* const* d_in, const int* in_sizes, int n_in,
                              void* d_out, int out_size) {
    const float* x = (const float*)d_in[0];
    int n = in_sizes[0] / 64;
    if (n > NMAX) n = NMAX;

    const int* src_arr;
    const int* dst_arr;
    int E, wbase;
    if (n_in >= 15) {
        src_arr = (const int*)d_in[1];
        dst_arr = (const int*)d_in[2];
        E = in_sizes[1];
        wbase = 3;
    } else {
        E = in_sizes[1] / 2;
        src_arr = (const int*)d_in[1];
        dst_arr = src_arr + E;
        wbase = 2;
    }
    if (E > EMAX) E = EMAX;

    const float* Wl1 = (const float*)d_in[wbase + 0];
    const float* bl1 = (const float*)d_in[wbase + 1];
    const float* Wr1 = (const float*)d_in[wbase + 2];
    const float* g1  = (const float*)d_in[wbase + 3];
    const float* b1  = (const float*)d_in[wbase + 4];
    const float* Wl2 = (const float*)d_in[wbase + 5];
    const float* bl2 = (const float*)d_in[wbase + 6];
    const float* Wr2 = (const float*)d_in[wbase + 7];
    const float* g2  = (const float*)d_in[wbase + 8];
    const float* b2  = (const float*)d_in[wbase + 9];
    const float* Wfc = (const float*)d_in[wbase + 10];
    const float* bfc = (const float*)d_in[wbase + 11];

    float* out0 = (float*)d_out;
    float* out1 = out0 + (size_t)n * 64;

    int agg16Grid = (int)(((size_t)n * 16 + 255) / 256);
    int warpGrid  = (int)(((size_t)n * 32 + 255) / 256);
    int cvtGrid   = (int)(((size_t)n * 32 + 255) / 256);
    int gemmGrid = (n + 127) / 128;
    const int GEMM_SMEM = 2 * 128 * APITCH * 4;  // 69632 B

    cudaFuncSetAttribute(gemm_kernel<1>, cudaFuncAttributeMaxDynamicSharedMemorySize, GEMM_SMEM);
    cudaFuncSetAttribute(gemm_kernel<2>, cudaFuncAttributeMaxDynamicSharedMemorySize, GEMM_SMEM);

    hist_kernel<<<(E + 255) / 256, 256>>>(dst_arr, E, n);
    alloc_cvt_kernel<<<cvtGrid, 256>>>(x, n);
    fill_kernel<<<(E + 255) / 256, 256>>>(src_arr, dst_arr, E, n);

    // layer 1 (agg64 is the 4th launch -> profiled by ncu)
    agg64_kernel<<<agg16Grid, 256>>>(n);
    gemm_kernel<1><<<gemmGrid, 256, GEMM_SMEM>>>(Wl1, Wr1, bl1, n);
    statsfin128_kernel<<<STATS_BLOCKS, 256>>>(g1, b1, n);

    // layer 2
    gemm_kernel<2><<<gemmGrid, 256, GEMM_SMEM>>>(Wl2, Wr2, nullptr, n);
    agg2_kernel<<<agg16Grid, 256>>>(bl2, out0, n);
    statsfin64_kernel<<<STATS_BLOCKS, 256>>>(out0, g2, b2, n);

    final_kernel<<<warpGrid, 256>>>(Wfc, bfc, out0, out1, n);
}